// round 15
// baseline (speedup 1.0000x reference)
#include <cuda_runtime.h>
#include <cuda_bf16.h>
#include <math.h>

#define BSZ  256
#define NN   1024
#define TT   100
#define NBLK 128
#define NTHR 256
#define TM   64
#define TN   64
#define KHALF 512
#define KC   32
#define NCH  16
#define STAGE 16384   // A 8K (h|l per 128B row) | B_h 4K | B_l 4K
#define NSTG  3
#define SMEM_TOTAL (NSTG * STAGE)   // 49152 = default limit, no attribute

// Output layout (floats)
#define O_ACT 0
#define O_E3H 512
#define O_E5H (512 + 102400)
#define O_C1H (512 + 2*102400)
#define O_E3F (512 + 3*102400)
#define O_E5F (O_E3F + 262144)
#define O_C1F (O_E5F + 262144)

// ---- persistent device state ----
__device__ float g_ec5[BSZ*NN];
__device__ float g_ec3[BSZ*NN];
__device__ float g_ca1[BSZ*NN];
__device__ float g_drive[TT*NN];
__device__ float g_part[NBLK * TM * TN];    // split-K partials, 2MB
__device__ __align__(16) __nv_bfloat16 g_ec3h[BSZ*NN], g_ec3l[BSZ*NN];
__device__ __align__(16) __nv_bfloat16 g_ca1h[BSZ*NN], g_ca1l[BSZ*NN];
__device__ __align__(16) __nv_bfloat16 g_ca3h[128*NN], g_ca3l[128*NN];
__device__ __align__(16) __nv_bfloat16 g_w0h[NN*NN], g_w0l[NN*NN];  // wca3ca1 [k][n]
__device__ __align__(16) __nv_bfloat16 g_w1h[NN*NN], g_w1l[NN*NN];  // wec3ca1 [k][n]
__device__ __align__(16) __nv_bfloat16 g_w2h[NN*NN], g_w2l[NN*NN];  // wca1ec5 [k][n]
__device__ unsigned g_full = 0;
__device__ unsigned g_grp[4 * 32];     // 4 m-groups of 32 CTAs
__device__ unsigned g_pair[64 * 32];   // 64 CTA pairs, 128B apart

__device__ __forceinline__ float sigm(float x) {
    return __fdividef(1.0f, 1.0f + __expf(-x));
}
__device__ __forceinline__ unsigned smem_u32(const void* p) {
    unsigned a;
    asm("{ .reg .u64 t; cvta.to.shared.u64 t, %1; cvt.u32.u64 %0, t; }" : "=r"(a) : "l"(p));
    return a;
}
#define SWZ128(o) ((unsigned)(o) ^ ((((unsigned)(o)) >> 3) & 0x70u))
#define CP_ASYNC16(dst, src) \
    asm volatile("cp.async.cg.shared.global [%0], [%1], 16;" :: "r"(dst), "l"(src) : "memory")
#define CP_COMMIT()  asm volatile("cp.async.commit_group;" ::: "memory")
#define CP_WAIT1()   asm volatile("cp.async.wait_group 1;" ::: "memory")

__device__ __forceinline__ void ldm_a(unsigned (&r)[4], unsigned a) {
    asm volatile("ldmatrix.sync.aligned.m8n8.x4.shared.b16 {%0,%1,%2,%3}, [%4];"
        : "=r"(r[0]), "=r"(r[1]), "=r"(r[2]), "=r"(r[3]) : "r"(a));
}
__device__ __forceinline__ void ldm_bt(unsigned (&r)[4], unsigned a) {
    asm volatile("ldmatrix.sync.aligned.m8n8.x4.trans.shared.b16 {%0,%1,%2,%3}, [%4];"
        : "=r"(r[0]), "=r"(r[1]), "=r"(r[2]), "=r"(r[3]) : "r"(a));
}
__device__ __forceinline__ void mma16816(float (&d)[4], const unsigned (&a)[4],
                                         unsigned b0, unsigned b1) {
    asm volatile(
        "mma.sync.aligned.m16n8k16.row.col.f32.bf16.bf16.f32 "
        "{%0,%1,%2,%3}, {%4,%5,%6,%7}, {%8,%9}, {%0,%1,%2,%3};"
        : "+f"(d[0]), "+f"(d[1]), "+f"(d[2]), "+f"(d[3])
        : "r"(a[0]), "r"(a[1]), "r"(a[2]), "r"(a[3]), "r"(b0), "r"(b1));
}

// Ticket barrier (race-free, wrap-safe; N power of 2)
__device__ __forceinline__ void ticket_sync(unsigned* ctr, unsigned N) {
    __syncthreads();
    if (threadIdx.x == 0) {
        __threadfence();
        const unsigned r    = atomicAdd(ctr, 1u);
        const unsigned goal = (r & ~(N - 1u)) + N;
        while ((*(volatile unsigned*)ctr) - r < goal - r) { }
        __threadfence();
    }
    __syncthreads();
}
#define FULL_SYNC()    ticket_sync(&g_full, NBLK)
#define GROUP_SYNC(g)  ticket_sync(&g_grp[(g) << 5], 32u)
#define PAIR_SYNC(p)   ticket_sync(&g_pair[(p) << 5], 2u)

// bf16-split HMMA, 64x64 tile over one K-half (512), 256 threads (8 warps),
// KC=32, cp.async 3-stage x 16KB. Warp: wm=warp>>1 (m16), wn=warp&1 (n32).
__device__ __forceinline__ void gemm64(
    const __nv_bfloat16* __restrict__ Ah, const __nv_bfloat16* __restrict__ Al,
    const __nv_bfloat16* __restrict__ Bh, const __nv_bfloat16* __restrict__ Bl,
    int n0, int k0, unsigned smb, float (&vv)[4][4])
{
    const int tid  = threadIdx.x;
    const int warp = tid >> 5, lane = tid & 31;
    const int wm = warp >> 1, wn = warp & 1;
    const int sel = lane >> 3, r8 = lane & 7;

    float v0[4][4], v1[4][4];   // v0 = hh ; v1 = hl + lh
#pragma unroll
    for (int nb = 0; nb < 4; nb++)
#pragma unroll
        for (int e = 0; e < 4; e++) { v0[nb][e] = 0.f; v1[nb][e] = 0.f; }

    // Loaders (4 quads/thread/chunk, coalesced; quad = tid-linear per region):
    // A region 8KB: 64 rows x 128B; row = [32k hi (64B) | 32k lo (64B)].
    const int r0 = tid >> 3, c0 = tid & 7;   // rows 0..31 ; quad col 0..7
    const int r1 = r0 + 32;                  // rows 32..63
    const unsigned dA0 = SWZ128(r0 * 128 + c0 * 16);
    const unsigned dA1 = SWZ128(r1 * 128 + c0 * 16);
    const __nv_bfloat16* aA0 = (c0 < 4 ? Ah + r0 * NN + k0 + c0 * 8
                                       : Al + r0 * NN + k0 + (c0 - 4) * 8);
    const __nv_bfloat16* aA1 = (c0 < 4 ? Ah + r1 * NN + k0 + c0 * 8
                                       : Al + r1 * NN + k0 + (c0 - 4) * 8);
    // B regions 4KB each: 32 k-rows x 128B (64 n cols).
    const unsigned dBq = SWZ128(r0 * 128 + c0 * 16);
    const __nv_bfloat16* aBh = Bh + (k0 + r0) * NN + n0 + c0 * 8;
    const __nv_bfloat16* aBl = Bl + (k0 + r0) * NN + n0 + c0 * 8;

    // ldmatrix tile-local offsets (pre-swizzle)
    const unsigned a_off = (unsigned)((wm * 16 + ((sel & 1) << 3) + r8) * 128
                                      + ((sel >> 1) << 4));
    const unsigned b_row = (unsigned)((((sel & 1) << 3) + r8) * 128);
    const unsigned b_c0  = (unsigned)((wn << 6) + ((sel >> 1) << 4));
    const unsigned b_c1  = b_c0 + 32;

    // prologue: chunks 0,1
#pragma unroll
    for (int c = 0; c < 2; c++) {
        const unsigned sb = smb + c * STAGE;
        const int ka = c * KC;
        const long long kb = (long long)ka * NN;
        CP_ASYNC16(sb + dA0,         aA0 + ka);
        CP_ASYNC16(sb + dA1,         aA1 + ka);
        CP_ASYNC16(sb + 8192 + dBq,  aBh + kb);
        CP_ASYNC16(sb + 12288 + dBq, aBl + kb);
        CP_COMMIT();
    }

    for (int c = 0; c < NCH; c++) {
        CP_WAIT1();
        __syncthreads();

        if (c + 2 < NCH) {
            const unsigned sb = smb + ((c + 2) % NSTG) * STAGE;
            const int ka = (c + 2) * KC;
            const long long kb = (long long)ka * NN;
            CP_ASYNC16(sb + dA0,         aA0 + ka);
            CP_ASYNC16(sb + dA1,         aA1 + ka);
            CP_ASYNC16(sb + 8192 + dBq,  aBh + kb);
            CP_ASYNC16(sb + 12288 + dBq, aBl + kb);
        }
        CP_COMMIT();

        const unsigned ab = smb + (c % NSTG) * STAGE;
#pragma unroll
        for (int ks = 0; ks < 2; ks++) {
            unsigned ah[4], al4[4], bh0[4], bh1[4], bl0[4], bl1[4];
            ldm_a(ah,   ab + SWZ128(a_off + ks * 32));
            ldm_a(al4,  ab + SWZ128(a_off + ks * 32 + 64));
            const unsigned br = b_row + ks * 2048;
            ldm_bt(bh0, ab + 8192 + SWZ128(br + b_c0));
            ldm_bt(bh1, ab + 8192 + SWZ128(br + b_c1));
            ldm_bt(bl0, ab + 12288 + SWZ128(br + b_c0));
            ldm_bt(bl1, ab + 12288 + SWZ128(br + b_c1));
            // hh
            mma16816(v0[0], ah, bh0[0], bh0[1]); mma16816(v0[1], ah, bh0[2], bh0[3]);
            mma16816(v0[2], ah, bh1[0], bh1[1]); mma16816(v0[3], ah, bh1[2], bh1[3]);
            // hl
            mma16816(v1[0], ah, bl0[0], bl0[1]); mma16816(v1[1], ah, bl0[2], bl0[3]);
            mma16816(v1[2], ah, bl1[0], bl1[1]); mma16816(v1[3], ah, bl1[2], bl1[3]);
            // lh
            mma16816(v1[0], al4, bh0[0], bh0[1]); mma16816(v1[1], al4, bh0[2], bh0[3]);
            mma16816(v1[2], al4, bh1[0], bh1[1]); mma16816(v1[3], al4, bh1[2], bh1[3]);
        }
    }

#pragma unroll
    for (int nb = 0; nb < 4; nb++)
#pragma unroll
        for (int e = 0; e < 4; e++)
            vv[nb][e] = v0[nb][e] + v1[nb][e];
}

// Store this CTA's 64x64 fp32 partial to g_part[b].
__device__ __forceinline__ void store_partial(int b, const float (&vv)[4][4]) {
    const int tid  = threadIdx.x;
    const int warp = tid >> 5, lane = tid & 31;
    const int wm = warp >> 1, wn = warp & 1;
    const int tr = lane >> 2, tc = (lane & 3) * 2;
    float* P = g_part + b * (TM * TN);
#pragma unroll
    for (int nb = 0; nb < 4; nb++)
#pragma unroll
        for (int e = 0; e < 4; e++) {
            const int ml = wm * 16 + tr + ((e >> 1) << 3);
            const int nl = wn * 32 + nb * 8 + tc + (e & 1);
            P[ml * TN + nl] = vv[nb][e];
        }
}

extern "C" __global__ void __launch_bounds__(NTHR, 1) rnn_kernel(
    const unsigned* __restrict__ cue,
    const float* __restrict__ ec3_last,
    const float* __restrict__ ec5_last,
    const float* __restrict__ ca1bias,
    const float* __restrict__ wca3ca1,
    const float* __restrict__ wec3ca1,
    const float* __restrict__ wca1ec5,
    const float* __restrict__ wca1act,
    const float* __restrict__ actbias,
    float* __restrict__ out)
{
    extern __shared__ char sm[];
    const unsigned smb = smem_u32(sm);

    const int tid  = threadIdx.x;
    const int b    = blockIdx.x;
    const int pair = b >> 1;        // tile id 0..63
    const int kh   = b & 1;         // K-half
    const int m0   = (pair >> 4) * TM;
    const int n0   = (pair & 15) * TN;
    const int k0   = kh * KHALF;
    const int grp  = b >> 5;        // 4 m-groups of 32 CTAs

    // ---- phase 0: state copy+split, ca3 split, weight split ----
    {
        const int gs = NBLK * NTHR;
        for (int i = b * NTHR + tid; i < BSZ * NN; i += gs) {
            const float e3 = ec3_last[i], e5 = ec5_last[i];
            g_ec3[i] = e3; g_ec5[i] = e5;
            const __nv_bfloat16 h = __float2bfloat16_rn(e3);
            g_ec3h[i] = h;
            g_ec3l[i] = __float2bfloat16_rn(e3 - __bfloat162float(h));
        }
        for (int i = b * NTHR + tid; i < 128 * NN; i += gs) {
            const int trow = i >> 10, k = i & 1023;
            float v = 0.0f;
            if (trow < TT) {
                const float c = (100.0f / 1023.0f) * (float)k;   // linspace(0,100,1024)
                const float dd = c - (float)trow;
                v = expf(-dd * dd * 0.02f);
            }
            const __nv_bfloat16 h = __float2bfloat16_rn(v);
            g_ca3h[i] = h;
            g_ca3l[i] = __float2bfloat16_rn(v - __bfloat162float(h));
        }
        for (int i = b * NTHR + tid; i < NN * NN; i += gs) {
            const float v0 = wca3ca1[i];
            const float v1 = wec3ca1[i];
            const float v2 = wca1ec5[i];
            const __nv_bfloat16 h0 = __float2bfloat16_rn(v0);
            const __nv_bfloat16 h1 = __float2bfloat16_rn(v1);
            const __nv_bfloat16 h2 = __float2bfloat16_rn(v2);
            g_w0h[i] = h0; g_w0l[i] = __float2bfloat16_rn(v0 - __bfloat162float(h0));
            g_w1h[i] = h1; g_w1l[i] = __float2bfloat16_rn(v1 - __bfloat162float(h1));
            g_w2h[i] = h2; g_w2l[i] = __float2bfloat16_rn(v2 - __bfloat162float(h2));
        }
    }
    FULL_SYNC();

    // ---- GEMM0: drive = ca3all @ wca3ca1 (M=100 pad 128 = 2 m-tiles), CTAs 0..63 ----
    if (b < 64) {
        const int pr = b >> 1, kh0 = b & 1;
        const int mm0 = (pr >> 4) * TM, nn0 = (pr & 15) * TN;
        float vv[4][4];
        gemm64(g_ca3h + mm0 * NN, g_ca3l + mm0 * NN, g_w0h, g_w0l,
               nn0, kh0 * KHALF, smb, vv);
        store_partial(b, vv);
        PAIR_SYNC(pr);
        const float* P0 = g_part + (pr * 2) * (TM * TN);
        const float* P1 = P0 + TM * TN;
        for (int i = tid; i < 32 * TN; i += NTHR) {
            const int r = i >> 6, cl = i & 63;
            const int ml = kh0 * 32 + r;
            const int m = mm0 + ml;
            if (m < TT)
                g_drive[m * NN + nn0 + cl] = P0[ml * TN + cl] + P1[ml * TN + cl];
        }
    }
    FULL_SYNC();

    // ---- recurrent scan: 4 m-groups of 32 CTAs ----
    for (int t = 0; t < TT; t++) {
        float vv[4][4];

        // GEMM1: ca1 = relu(drive_t * (1+sigm(ec3@W1)) - bias)
        gemm64(g_ec3h + m0 * NN, g_ec3l + m0 * NN, g_w1h, g_w1l, n0, k0, smb, vv);
        store_partial(b, vv);
        PAIR_SYNC(pair);
        {
            const float* P0 = g_part + (pair * 2) * (TM * TN);
            const float* P1 = P0 + TM * TN;
            for (int i = tid; i < 32 * TN; i += NTHR) {
                const int r = i >> 6, cl = i & 63;
                const int ml = kh * 32 + r;
                const int m = m0 + ml, n = n0 + cl;
                const int idx = m * NN + n;
                float val = g_drive[t * NN + n]
                            * (1.0f + sigm(P0[ml * TN + cl] + P1[ml * TN + cl]))
                            - ca1bias[n];
                val = fmaxf(val, 0.0f);
                g_ca1[idx] = val;
                const __nv_bfloat16 hb = __float2bfloat16_rn(val);
                g_ca1h[idx] = hb;
                g_ca1l[idx] = __float2bfloat16_rn(val - __bfloat162float(hb));
                if (m == 0)      out[O_C1H + t * NN + n] = val;
                if (t == TT - 1) out[O_C1F + idx] = val;
            }
        }
        GROUP_SYNC(grp);

        // GEMM2: ec5' = squash(ec5 + ca1@W2); ec3' = ec5'*ec3 (+ cue mask)
        gemm64(g_ca1h + m0 * NN, g_ca1l + m0 * NN, g_w2h, g_w2l, n0, k0, smb, vv);
        store_partial(b, vv);
        PAIR_SYNC(pair);
        {
            const float* P0 = g_part + (pair * 2) * (TM * TN);
            const float* P1 = P0 + TM * TN;
            for (int i = tid; i < 32 * TN; i += NTHR) {
                const int r = i >> 6, cl = i & 63;
                const int ml = kh * 32 + r;
                const int m = m0 + ml, n = n0 + cl;
                const int idx = m * NN + n;
                float e5 = g_ec5[idx] + P0[ml * TN + cl] + P1[ml * TN + cl];
                e5 = 0.69f + 0.3f * sigm(4.0f * (e5 - 0.3f));
                float e3 = e5 * g_ec3[idx];
                // cueloc = 8*(s+2): t==16 -> cue[:,0,:], t==24 -> cue[:,1,:]
                if (t == 16 && cue[m * 2048 + n]        != 0u) e3 = 0.4f * e3 + 0.6f;
                if (t == 24 && cue[m * 2048 + 1024 + n] != 0u) e3 = 0.4f * e3 + 0.6f;
                g_ec5[idx] = e5;
                g_ec3[idx] = e3;
                const __nv_bfloat16 hb = __float2bfloat16_rn(e3);
                g_ec3h[idx] = hb;
                g_ec3l[idx] = __float2bfloat16_rn(e3 - __bfloat162float(hb));
                if (m == 0) {
                    out[O_E3H + t * NN + n] = e3;
                    out[O_E5H + t * NN + n] = e5;
                }
                if (t == TT - 1) {
                    out[O_E3F + idx] = e3;
                    out[O_E5F + idx] = e5;
                }
            }
        }
        GROUP_SYNC(grp);
    }

    // ---- actCell = ca1_final @ wca1act + actbias (rows 2b, 2b+1) ----
    {
        const int warp = tid >> 5, lane = tid & 31;
        if (warp < 4) {
            const int r = 2 * b + (warp >> 1);
            const int a = warp & 1;
            float s = 0.0f;
            for (int k = lane; k < NN; k += 32)
                s = fmaf(g_ca1[r * NN + k], wca1act[k * 2 + a], s);
#pragma unroll
            for (int off = 16; off; off >>= 1)
                s += __shfl_xor_sync(0xffffffffu, s, off);
            if (lane == 0) out[O_ACT + r * 2 + a] = s + actbias[a];
        }
    }
}

extern "C" void kernel_launch(void* const* d_in, const int* in_sizes, int n_in,
                              void* d_out, int out_size)
{
    // metadata order: cue, ec3_last, ec5_last, ca1_last, ca1bias, wca3ca1,
    //                 wec3ca1, wca1ec5, wca1act, actbias
    rnn_kernel<<<NBLK, NTHR, SMEM_TOTAL>>>(
        (const unsigned*)d_in[0],
        (const float*)d_in[1],
        (const float*)d_in[2],
        (const float*)d_in[4],
        (const float*)d_in[5],
        (const float*)d_in[6],
        (const float*)d_in[7],
        (const float*)d_in[8],
        (const float*)d_in[9],
        (float*)d_out);
}

// round 17
// speedup vs baseline: 1.1950x; 1.1950x over previous
#include <cuda_runtime.h>
#include <cuda_bf16.h>
#include <math.h>

#define BSZ  256
#define NN   1024
#define TT   100
#define NBLK 256
#define NTHR 128
#define TM   32
#define TN   32
#define KC   64
#define NCH  16
#define STAGE 16384         // A_h 4K | A_l 4K | B 8K (32n h | 32n l per 128B k-row)
#define NSTG  3
#define SMEM_TOTAL (NSTG * STAGE)   // 49152; 3 CTAs/SM = 144KB smem

// Output layout (floats)
#define O_ACT 0
#define O_E3H 512
#define O_E5H (512 + 102400)
#define O_C1H (512 + 2*102400)
#define O_E3F (512 + 3*102400)
#define O_E5F (O_E3F + 262144)
#define O_C1F (O_E5F + 262144)

// ---- persistent device state ----
__device__ float g_ec5[BSZ*NN];
__device__ float g_ec3[BSZ*NN];
__device__ float g_ca1[BSZ*NN];
__device__ float g_drive[TT*NN];
__device__ __align__(16) __nv_bfloat16 g_ec3h[BSZ*NN], g_ec3l[BSZ*NN];
__device__ __align__(16) __nv_bfloat16 g_ca1h[BSZ*NN], g_ca1l[BSZ*NN];
__device__ __align__(16) __nv_bfloat16 g_ca3h[128*NN], g_ca3l[128*NN];
__device__ __align__(16) __nv_bfloat16 g_w0h[NN*NN], g_w0l[NN*NN];  // wca3ca1 [k][n]
__device__ __align__(16) __nv_bfloat16 g_w1h[NN*NN], g_w1l[NN*NN];  // wec3ca1 [k][n]
__device__ __align__(16) __nv_bfloat16 g_w2h[NN*NN], g_w2l[NN*NN];  // wca1ec5 [k][n]
__device__ unsigned g_full = 0;
__device__ unsigned g_grp[8 * 32];

__device__ __forceinline__ float sigm(float x) {
    return __fdividef(1.0f, 1.0f + __expf(-x));
}
__device__ __forceinline__ unsigned smem_u32(const void* p) {
    unsigned a;
    asm("{ .reg .u64 t; cvta.to.shared.u64 t, %1; cvt.u32.u64 %0, t; }" : "=r"(a) : "l"(p));
    return a;
}
#define SWZ128(o) ((unsigned)(o) ^ ((((unsigned)(o)) >> 3) & 0x70u))
#define CP_ASYNC16(dst, src) \
    asm volatile("cp.async.cg.shared.global [%0], [%1], 16;" :: "r"(dst), "l"(src) : "memory")
#define CP_COMMIT()  asm volatile("cp.async.commit_group;" ::: "memory")
#define CP_WAIT1()   asm volatile("cp.async.wait_group 1;" ::: "memory")

__device__ __forceinline__ void ldm_a(unsigned (&r)[4], unsigned a) {
    asm volatile("ldmatrix.sync.aligned.m8n8.x4.shared.b16 {%0,%1,%2,%3}, [%4];"
        : "=r"(r[0]), "=r"(r[1]), "=r"(r[2]), "=r"(r[3]) : "r"(a));
}
__device__ __forceinline__ void ldm_bt(unsigned (&r)[4], unsigned a) {
    asm volatile("ldmatrix.sync.aligned.m8n8.x4.trans.shared.b16 {%0,%1,%2,%3}, [%4];"
        : "=r"(r[0]), "=r"(r[1]), "=r"(r[2]), "=r"(r[3]) : "r"(a));
}
__device__ __forceinline__ void mma16816(float (&d)[4], const unsigned (&a)[4],
                                         unsigned b0, unsigned b1) {
    asm volatile(
        "mma.sync.aligned.m16n8k16.row.col.f32.bf16.bf16.f32 "
        "{%0,%1,%2,%3}, {%4,%5,%6,%7}, {%8,%9}, {%0,%1,%2,%3};"
        : "+f"(d[0]), "+f"(d[1]), "+f"(d[2]), "+f"(d[3])
        : "r"(a[0]), "r"(a[1]), "r"(a[2]), "r"(a[3]), "r"(b0), "r"(b1));
}

// Ticket barrier (race-free, wrap-safe; N power of 2)
__device__ __forceinline__ void ticket_sync(unsigned* ctr, unsigned N) {
    __syncthreads();
    if (threadIdx.x == 0) {
        __threadfence();
        const unsigned r    = atomicAdd(ctr, 1u);
        const unsigned goal = (r & ~(N - 1u)) + N;
        while ((*(volatile unsigned*)ctr) - r < goal - r) { }
        __threadfence();
    }
    __syncthreads();
}
#define FULL_SYNC()    ticket_sync(&g_full, NBLK)
#define GROUP_SYNC(g)  ticket_sync(&g_grp[(g) << 5], 32u)

// bf16-split HMMA GEMM, 32x32 tile over K=1024, 128 threads, KC=64 chunks,
// cp.async 3-stage. Warp: wm=warp>>1 (m16), wn=warp&1 (n16).
// Two accumulator sets: v0 = hh, v1 = hl + lh (identical sum, fewer regs).
__device__ __forceinline__ void gemm32(
    const __nv_bfloat16* __restrict__ Ah, const __nv_bfloat16* __restrict__ Al,
    const __nv_bfloat16* __restrict__ Bh, const __nv_bfloat16* __restrict__ Bl,
    int n0, unsigned smb, float (&v)[2][4])
{
    const int tid  = threadIdx.x;
    const int warp = tid >> 5, lane = tid & 31;
    const int wm = warp >> 1, wn = warp & 1;
    const int sel = lane >> 3, r8 = lane & 7;

    float v0[2][4], v1[2][4];
#pragma unroll
    for (int nb = 0; nb < 2; nb++)
#pragma unroll
        for (int e = 0; e < 4; e++) { v0[nb][e] = 0.f; v1[nb][e] = 0.f; }

    // A regions: 32 rows x 8 quads = 256 quads each (h, l); thread does quads
    // tid, tid+128 -> every instruction covers consecutive quads (coalesced).
    const int ar0 = tid >> 3, aq = tid & 7;
    const unsigned dA0 = SWZ128(ar0 * 128 + aq * 16);
    const unsigned dA1 = SWZ128((ar0 + 16) * 128 + aq * 16);
    const __nv_bfloat16* sAh0 = Ah + ar0 * NN + aq * 8;
    const __nv_bfloat16* sAh1 = Ah + (ar0 + 16) * NN + aq * 8;
    const __nv_bfloat16* sAl0 = Al + ar0 * NN + aq * 8;
    const __nv_bfloat16* sAl1 = Al + (ar0 + 16) * NN + aq * 8;
    // B region: 64 k-rows x 8 quads = 512 quads; quad q: row=q>>3, c=q&7
    // (c<4 -> hi cols, else lo cols). Thread does q = tid + {0,128,256,384}.
    unsigned dB[4];
    const __nv_bfloat16* sB[4];
#pragma unroll
    for (int j = 0; j < 4; j++) {
        const int q = tid + j * 128;
        const int rr = q >> 3, cc = q & 7;
        dB[j] = 8192 + SWZ128(rr * 128 + cc * 16);
        sB[j] = (cc < 4 ? Bh + rr * NN + n0 + cc * 8
                        : Bl + rr * NN + n0 + (cc - 4) * 8);
    }

    // ldmatrix tile-local offsets (pre-swizzle)
    const unsigned a_off = (unsigned)((wm * 16 + ((sel & 1) << 3) + r8) * 128
                                      + ((sel >> 1) << 4));
    const unsigned b_off = (unsigned)((((sel & 1) << 3) + r8) * 128
                                      + (wn << 5) + ((sel >> 1) << 4));

    // prologue: issue chunks 0,1
#pragma unroll
    for (int c = 0; c < 2; c++) {
        const unsigned sb = smb + c * STAGE;
        const int ka = c * KC;
        const long long kb = (long long)ka * NN;
        CP_ASYNC16(sb + dA0,        sAh0 + ka);
        CP_ASYNC16(sb + dA1,        sAh1 + ka);
        CP_ASYNC16(sb + 4096 + dA0, sAl0 + ka);
        CP_ASYNC16(sb + 4096 + dA1, sAl1 + ka);
#pragma unroll
        for (int j = 0; j < 4; j++) CP_ASYNC16(sb + dB[j], sB[j] + kb);
        CP_COMMIT();
    }

    for (int c = 0; c < NCH; c++) {
        CP_WAIT1();            // chunk c landed (per-thread)
        __syncthreads();       // all threads' waits done; prev compute done

        if (c + 2 < NCH) {     // issue chunk c+2 into freed stage
            const unsigned sb = smb + ((c + 2) % NSTG) * STAGE;
            const int ka = (c + 2) * KC;
            const long long kb = (long long)ka * NN;
            CP_ASYNC16(sb + dA0,        sAh0 + ka);
            CP_ASYNC16(sb + dA1,        sAh1 + ka);
            CP_ASYNC16(sb + 4096 + dA0, sAl0 + ka);
            CP_ASYNC16(sb + 4096 + dA1, sAl1 + ka);
#pragma unroll
            for (int j = 0; j < 4; j++) CP_ASYNC16(sb + dB[j], sB[j] + kb);
        }
        CP_COMMIT();           // every iter commits exactly one group

        const unsigned ab = smb + (c % NSTG) * STAGE;
#pragma unroll
        for (int ks = 0; ks < 4; ks++) {
            unsigned ah[4], al4[4], bh[4], bl[4];
            ldm_a(ah,  ab + SWZ128(a_off + ks * 32));
            ldm_a(al4, ab + 4096 + SWZ128(a_off + ks * 32));
            const unsigned bo = b_off + ks * 2048;      // 16 k-rows per ks
            ldm_bt(bh, ab + 8192 + SWZ128(bo));
            ldm_bt(bl, ab + 8192 + SWZ128(bo + 64));
            mma16816(v0[0], ah,  bh[0], bh[1]);
            mma16816(v0[1], ah,  bh[2], bh[3]);
            mma16816(v1[0], ah,  bl[0], bl[1]);
            mma16816(v1[1], ah,  bl[2], bl[3]);
            mma16816(v1[0], al4, bh[0], bh[1]);
            mma16816(v1[1], al4, bh[2], bh[3]);
        }
    }

#pragma unroll
    for (int nb = 0; nb < 2; nb++)
#pragma unroll
        for (int e = 0; e < 4; e++)
            v[nb][e] = v0[nb][e] + v1[nb][e];
}

extern "C" __global__ void __launch_bounds__(NTHR, 3) rnn_kernel(
    const unsigned* __restrict__ cue,
    const float* __restrict__ ec3_last,
    const float* __restrict__ ec5_last,
    const float* __restrict__ ca1bias,
    const float* __restrict__ wca3ca1,
    const float* __restrict__ wec3ca1,
    const float* __restrict__ wca1ec5,
    const float* __restrict__ wca1act,
    const float* __restrict__ actbias,
    float* __restrict__ out)
{
    extern __shared__ char sm[];
    const unsigned smb = smem_u32(sm);

    const int tid  = threadIdx.x;
    const int b    = blockIdx.x;
    const int warp = tid >> 5, lane = tid & 31;
    const int wm = warp >> 1, wn = warp & 1;
    const int tr = lane >> 2, tc = (lane & 3) * 2;
    const int grp = b >> 5;                  // 8 groups of 32 CTAs
    const int m0  = grp * TM;
    const int n0  = (b & 31) * TN;

    // ---- phase 0: state copy+split, ca3 split, weight split ----
    {
        const int gs = NBLK * NTHR;
        for (int i = b * NTHR + tid; i < BSZ * NN; i += gs) {
            const float e3 = ec3_last[i], e5 = ec5_last[i];
            g_ec3[i] = e3; g_ec5[i] = e5;
            const __nv_bfloat16 h = __float2bfloat16_rn(e3);
            g_ec3h[i] = h;
            g_ec3l[i] = __float2bfloat16_rn(e3 - __bfloat162float(h));
        }
        for (int i = b * NTHR + tid; i < 128 * NN; i += gs) {
            const int trow = i >> 10, k = i & 1023;
            float v = 0.0f;
            if (trow < TT) {
                const float c = (100.0f / 1023.0f) * (float)k;   // linspace(0,100,1024)
                const float dd = c - (float)trow;
                v = expf(-dd * dd * 0.02f);
            }
            const __nv_bfloat16 h = __float2bfloat16_rn(v);
            g_ca3h[i] = h;
            g_ca3l[i] = __float2bfloat16_rn(v - __bfloat162float(h));
        }
        for (int i = b * NTHR + tid; i < NN * NN; i += gs) {
            const float v0 = wca3ca1[i];
            const float v1 = wec3ca1[i];
            const float v2 = wca1ec5[i];
            const __nv_bfloat16 h0 = __float2bfloat16_rn(v0);
            const __nv_bfloat16 h1 = __float2bfloat16_rn(v1);
            const __nv_bfloat16 h2 = __float2bfloat16_rn(v2);
            g_w0h[i] = h0; g_w0l[i] = __float2bfloat16_rn(v0 - __bfloat162float(h0));
            g_w1h[i] = h1; g_w1l[i] = __float2bfloat16_rn(v1 - __bfloat162float(h1));
            g_w2h[i] = h2; g_w2l[i] = __float2bfloat16_rn(v2 - __bfloat162float(h2));
        }
    }
    FULL_SYNC();

    // ---- GEMM0: drive = ca3all @ wca3ca1 (M=100 pad 128), CTAs 0..127 ----
    if (b < 128) {
        const int m0g = (b >> 5) * TM;
        const int n0g = (b & 31) * TN;
        float v[2][4];
        gemm32(g_ca3h + m0g * NN, g_ca3l + m0g * NN, g_w0h, g_w0l, n0g, smb, v);
#pragma unroll
        for (int nb = 0; nb < 2; nb++)
#pragma unroll
            for (int e = 0; e < 4; e++) {
                const int m = m0g + wm * 16 + tr + ((e >> 1) << 3);
                const int n = n0g + wn * 16 + nb * 8 + tc + (e & 1);
                if (m < TT) g_drive[m * NN + n] = v[nb][e];
            }
    }
    FULL_SYNC();

    // ---- recurrent scan: 8 independent groups of 32 CTAs ----
    for (int t = 0; t < TT; t++) {
        float v[2][4];

        // GEMM1: ca1 = relu(drive_t * (1+sigm(ec3@W1)) - bias)
        gemm32(g_ec3h + m0 * NN, g_ec3l + m0 * NN, g_w1h, g_w1l, n0, smb, v);
#pragma unroll
        for (int nb = 0; nb < 2; nb++)
#pragma unroll
            for (int e = 0; e < 4; e++) {
                const int m = m0 + wm * 16 + tr + ((e >> 1) << 3);
                const int n = n0 + wn * 16 + nb * 8 + tc + (e & 1);
                const int idx = m * NN + n;
                float val = g_drive[t * NN + n] * (1.0f + sigm(v[nb][e])) - ca1bias[n];
                val = fmaxf(val, 0.0f);
                g_ca1[idx] = val;
                const __nv_bfloat16 hb = __float2bfloat16_rn(val);
                g_ca1h[idx] = hb;
                g_ca1l[idx] = __float2bfloat16_rn(val - __bfloat162float(hb));
                if (m == 0)      out[O_C1H + t * NN + n] = val;
                if (t == TT - 1) out[O_C1F + idx] = val;
            }
        GROUP_SYNC(grp);

        // GEMM2: ec5' = squash(ec5 + ca1@W2); ec3' = ec5'*ec3 (+ cue mask)
        gemm32(g_ca1h + m0 * NN, g_ca1l + m0 * NN, g_w2h, g_w2l, n0, smb, v);
#pragma unroll
        for (int nb = 0; nb < 2; nb++)
#pragma unroll
            for (int e = 0; e < 4; e++) {
                const int m = m0 + wm * 16 + tr + ((e >> 1) << 3);
                const int n = n0 + wn * 16 + nb * 8 + tc + (e & 1);
                const int idx = m * NN + n;
                float e5 = g_ec5[idx] + v[nb][e];
                e5 = 0.69f + 0.3f * sigm(4.0f * (e5 - 0.3f));
                float e3 = e5 * g_ec3[idx];
                // cueloc = 8*(s+2): t==16 -> cue[:,0,:], t==24 -> cue[:,1,:]
                if (t == 16 && cue[m * 2048 + n]        != 0u) e3 = 0.4f * e3 + 0.6f;
                if (t == 24 && cue[m * 2048 + 1024 + n] != 0u) e3 = 0.4f * e3 + 0.6f;
                g_ec5[idx] = e5;
                g_ec3[idx] = e3;
                const __nv_bfloat16 hb = __float2bfloat16_rn(e3);
                g_ec3h[idx] = hb;
                g_ec3l[idx] = __float2bfloat16_rn(e3 - __bfloat162float(hb));
                if (m == 0) {
                    out[O_E3H + t * NN + n] = e3;
                    out[O_E5H + t * NN + n] = e5;
                }
                if (t == TT - 1) {
                    out[O_E3F + idx] = e3;
                    out[O_E5F + idx] = e5;
                }
            }
        GROUP_SYNC(grp);
    }

    // ---- actCell = ca1_final @ wca1act + actbias (row b) ----
    {
        if (warp < 2) {
            const int a = warp;
            float s = 0.0f;
            for (int k = lane; k < NN; k += 32)
                s = fmaf(g_ca1[b * NN + k], wca1act[k * 2 + a], s);
#pragma unroll
            for (int off = 16; off; off >>= 1)
                s += __shfl_xor_sync(0xffffffffu, s, off);
            if (lane == 0) out[O_ACT + b * 2 + a] = s + actbias[a];
        }
    }
}

extern "C" void kernel_launch(void* const* d_in, const int* in_sizes, int n_in,
                              void* d_out, int out_size)
{
    // metadata order: cue, ec3_last, ec5_last, ca1_last, ca1bias, wca3ca1,
    //                 wec3ca1, wca1ec5, wca1act, actbias
    rnn_kernel<<<NBLK, NTHR, SMEM_TOTAL>>>(
        (const unsigned*)d_in[0],
        (const float*)d_in[1],
        (const float*)d_in[2],
        (const float*)d_in[4],
        (const float*)d_in[5],
        (const float*)d_in[6],
        (const float*)d_in[7],
        (const float*)d_in[8],
        (const float*)d_in[9],
        (float*)d_out);
}